// round 2
// baseline (speedup 1.0000x reference)
#include <cuda_runtime.h>
#include <math.h>

#define T_STEPS 256
#define INPUT   12288
#define HID     1024
#define GATES   4096

// ---------------- device scratch (no allocations allowed) ----------------
__device__ float        g_xproj[T_STEPS * GATES];   // 4 MB
__device__ float        g_h[2][HID];                // ping-pong hidden state
__device__ unsigned int g_bar;                      // monotonic barrier counter

// ---------------- helpers: packed f32x2 FMA ----------------
__device__ __forceinline__ unsigned long long dup2(float x) {
    unsigned long long r;
    asm("mov.b64 %0, {%1, %1};" : "=l"(r) : "f"(x));
    return r;
}
__device__ __forceinline__ void ffma2(unsigned long long& d,
                                      unsigned long long a,
                                      unsigned long long b) {
    asm("fma.rn.f32x2 %0, %1, %2, %0;" : "+l"(d) : "l"(a), "l"(b));
}
__device__ __forceinline__ void unpack2(unsigned long long v, float& lo, float& hi) {
    asm("mov.b64 {%0, %1}, %2;" : "=f"(lo), "=f"(hi) : "l"(v));
}

// ---------------- init: zero h0, reset barrier ----------------
__global__ void init_kernel() {
    int tid = blockIdx.x * blockDim.x + threadIdx.x;
    if (tid < HID) { g_h[0][tid] = 0.f; g_h[1][tid] = 0.f; }
    if (tid == 0) g_bar = 0u;
}

// ---------------- GEMM1: x_proj = frames @ W_ih^T + b_ih + b_hh ----------------
// C[256][4096], A[256][12288] row-major, B[4096][12288] row-major (both k-major)
#define BM 64
#define BN 128
#define BK 32
#define AP 68    // As row pad (floats), 272B (16B aligned)
#define BP 132   // Bs row pad (floats), 528B (16B aligned)
#define NT (INPUT / BK)   // 384 k-tiles

__global__ __launch_bounds__(256, 1)
void gemm1_kernel(const float* __restrict__ A,
                  const float* __restrict__ B,
                  const float* __restrict__ b_ih,
                  const float* __restrict__ b_hh) {
    __shared__ float As[BK][AP];
    __shared__ float Bs[BK][BP];

    const int tid = threadIdx.x;
    const int ty  = tid >> 4;    // 0..15 (m)
    const int tx  = tid & 15;    // 0..15 (n)
    const int m0  = blockIdx.y * BM;
    const int n0  = blockIdx.x * BN;

    unsigned long long acc[4][4];
#pragma unroll
    for (int i = 0; i < 4; i++)
#pragma unroll
        for (int j = 0; j < 4; j++) acc[i][j] = 0ULL;

    float4 aReg[2], bReg[4];

    // ---- load tile 0 into regs ----
#pragma unroll
    for (int p = 0; p < 2; p++) {
        int idx = tid + p * 256;
        int m = idx >> 3, kq = idx & 7;
        aReg[p] = *(const float4*)(A + (size_t)(m0 + m) * INPUT + kq * 4);
    }
#pragma unroll
    for (int p = 0; p < 4; p++) {
        int idx = tid + p * 256;
        int n = idx >> 3, kq = idx & 7;
        bReg[p] = *(const float4*)(B + (size_t)(n0 + n) * INPUT + kq * 4);
    }
    // ---- store tile 0 to smem (transposed) ----
#pragma unroll
    for (int p = 0; p < 2; p++) {
        int idx = tid + p * 256;
        int m = idx >> 3, kq = idx & 7;
        As[kq * 4 + 0][m] = aReg[p].x;
        As[kq * 4 + 1][m] = aReg[p].y;
        As[kq * 4 + 2][m] = aReg[p].z;
        As[kq * 4 + 3][m] = aReg[p].w;
    }
#pragma unroll
    for (int p = 0; p < 4; p++) {
        int idx = tid + p * 256;
        int n = idx >> 3, kq = idx & 7;
        Bs[kq * 4 + 0][n] = bReg[p].x;
        Bs[kq * 4 + 1][n] = bReg[p].y;
        Bs[kq * 4 + 2][n] = bReg[p].z;
        Bs[kq * 4 + 3][n] = bReg[p].w;
    }
    __syncthreads();

    for (int kt = 0; kt < NT; kt++) {
        // prefetch next tile's global data
        if (kt + 1 < NT) {
            int kbase = (kt + 1) * BK;
#pragma unroll
            for (int p = 0; p < 2; p++) {
                int idx = tid + p * 256;
                int m = idx >> 3, kq = idx & 7;
                aReg[p] = *(const float4*)(A + (size_t)(m0 + m) * INPUT + kbase + kq * 4);
            }
#pragma unroll
            for (int p = 0; p < 4; p++) {
                int idx = tid + p * 256;
                int n = idx >> 3, kq = idx & 7;
                bReg[p] = *(const float4*)(B + (size_t)(n0 + n) * INPUT + kbase + kq * 4);
            }
        }
        // compute on current smem tile
#pragma unroll
        for (int kk = 0; kk < BK; kk++) {
            float4 a4 = *(const float4*)&As[kk][ty * 4];
            unsigned long long av[4];
            av[0] = dup2(a4.x); av[1] = dup2(a4.y);
            av[2] = dup2(a4.z); av[3] = dup2(a4.w);
            unsigned long long bv[4];
#pragma unroll
            for (int jn = 0; jn < 4; jn++)
                bv[jn] = *(const unsigned long long*)&Bs[kk][tx * 8 + 2 * jn];
#pragma unroll
            for (int i = 0; i < 4; i++)
#pragma unroll
                for (int jn = 0; jn < 4; jn++)
                    ffma2(acc[i][jn], av[i], bv[jn]);
        }
        __syncthreads();
        if (kt + 1 < NT) {
#pragma unroll
            for (int p = 0; p < 2; p++) {
                int idx = tid + p * 256;
                int m = idx >> 3, kq = idx & 7;
                As[kq * 4 + 0][m] = aReg[p].x;
                As[kq * 4 + 1][m] = aReg[p].y;
                As[kq * 4 + 2][m] = aReg[p].z;
                As[kq * 4 + 3][m] = aReg[p].w;
            }
#pragma unroll
            for (int p = 0; p < 4; p++) {
                int idx = tid + p * 256;
                int n = idx >> 3, kq = idx & 7;
                Bs[kq * 4 + 0][n] = bReg[p].x;
                Bs[kq * 4 + 1][n] = bReg[p].y;
                Bs[kq * 4 + 2][n] = bReg[p].z;
                Bs[kq * 4 + 3][n] = bReg[p].w;
            }
            __syncthreads();
        }
    }

    // epilogue: add biases, store
#pragma unroll
    for (int i = 0; i < 4; i++) {
        int m = m0 + ty * 4 + i;
        float* crow = g_xproj + (size_t)m * GATES;
#pragma unroll
        for (int jn = 0; jn < 4; jn++) {
            int n = n0 + tx * 8 + 2 * jn;
            float lo, hi;
            unpack2(acc[i][jn], lo, hi);
            float2 v;
            v.x = lo + b_ih[n]     + b_hh[n];
            v.y = hi + b_ih[n + 1] + b_hh[n + 1];
            *(float2*)&crow[n] = v;
        }
    }
}

// ---------------- persistent LSTM scan ----------------
// 128 CTAs, 256 threads. CTA b owns hidden units [8b, 8b+8); warp w <-> unit 8b+w.
// W_hh slice (32 rows x 1024) resident in SMEM. Global spin barrier per step.
#define SCAN_CTAS 128
#define SCAN_SMEM (32 * 1024 * 4 + 1024 * 4)   // 135168 B

__global__ __launch_bounds__(256, 1)
void scan_kernel(const float* __restrict__ Whh) {
    extern __shared__ float smem[];
    float* Ws = smem;              // [32][1024]
    float* hs = smem + 32 * 1024;  // [1024]

    const int tid  = threadIdx.x;
    const int warp = tid >> 5;
    const int lane = tid & 31;
    const int b    = blockIdx.x;
    const int j    = b * 8 + warp;   // this warp's hidden unit

    // load W slice: local row (w*4 + g) <- global row (g*1024 + 8b + w)
    for (int idx = tid; idx < 32 * 256; idx += 256) {
        int lr = idx >> 8;       // 0..31
        int kq = idx & 255;      // float4 index
        int w = lr >> 2, g = lr & 3;
        int grow = g * 1024 + b * 8 + w;
        *(float4*)&Ws[lr * 1024 + kq * 4] =
            *(const float4*)&Whh[(size_t)grow * HID + kq * 4];
    }
    __syncthreads();

    float cstate = 0.f;

    for (int t = 0; t < T_STEPS; t++) {
        const float* hin  = g_h[t & 1];
        float*       hout = g_h[(t + 1) & 1];

        // stage h into smem
        *(float4*)&hs[tid * 4] = *(const float4*)&hin[tid * 4];
        __syncthreads();

        // x_proj contributions for this unit (uniform across warp -> broadcast)
        float xg0 = g_xproj[(size_t)t * GATES + 0 * HID + j];
        float xg1 = g_xproj[(size_t)t * GATES + 1 * HID + j];
        float xg2 = g_xproj[(size_t)t * GATES + 2 * HID + j];
        float xg3 = g_xproj[(size_t)t * GATES + 3 * HID + j];

        // h fragment: strided k-chunks (conflict-free LDS.128)
        ulonglong2 hf[8];
#pragma unroll
        for (int i = 0; i < 8; i++)
            hf[i] = *(const ulonglong2*)&hs[lane * 4 + i * 128];

        float red[4];
#pragma unroll
        for (int g = 0; g < 4; g++) {
            const float* wrow = &Ws[(warp * 4 + g) * 1024];
            unsigned long long a2 = 0ULL;
#pragma unroll
            for (int i = 0; i < 8; i++) {
                ulonglong2 wf = *(const ulonglong2*)&wrow[lane * 4 + i * 128];
                ffma2(a2, hf[i].x, wf.x);
                ffma2(a2, hf[i].y, wf.y);
            }
            float lo, hi;
            unpack2(a2, lo, hi);
            red[g] = lo + hi;
        }
        // butterfly reduce across the warp (all lanes get totals)
#pragma unroll
        for (int o = 16; o; o >>= 1) {
#pragma unroll
            for (int g = 0; g < 4; g++)
                red[g] += __shfl_xor_sync(0xffffffffu, red[g], o);
        }

        float gi = 1.f / (1.f + __expf(-(xg0 + red[0])));
        float gf = 1.f / (1.f + __expf(-(xg1 + red[1])));
        float gg = tanhf(xg2 + red[2]);
        float go = 1.f / (1.f + __expf(-(xg3 + red[3])));
        cstate = gf * cstate + gi * gg;
        float hnew = go * tanhf(cstate);

        if (lane == 0) hout[j] = hnew;

        // ---- global barrier: release arrive + acquire spin ----
        __threadfence();
        __syncthreads();   // all warps stored + fenced; also guards hs reuse
        if (tid == 0) {
            asm volatile("red.release.gpu.global.add.u32 [%0], 1;"
                         :: "l"(&g_bar) : "memory");
            unsigned int target = (unsigned int)SCAN_CTAS * (unsigned int)(t + 1);
            unsigned int v;
            do {
                asm volatile("ld.acquire.gpu.global.u32 %0, [%1];"
                             : "=r"(v) : "l"(&g_bar));
            } while (v < target);
        }
        __syncthreads();
    }
}

// ---------------- final: out = h_T @ fc_w^T + fc_b ----------------
__global__ __launch_bounds__(256, 2)
void final_kernel(const float* __restrict__ fcw,
                  const float* __restrict__ fcb,
                  float* __restrict__ out) {
    __shared__ float hs[HID];
    const int tid = threadIdx.x, warp = tid >> 5, lane = tid & 31;
    // h_T lives in g_h[0] (t=255 writes buffer (255+1)&1 = 0)
    *(float4*)&hs[tid * 4] = *(const float4*)&g_h[0][tid * 4];
    __syncthreads();

    int row = blockIdx.x * 8 + warp;   // 1536 blocks * 8 warps = 12288 rows
    const float* wr = fcw + (size_t)row * HID;
    float acc = 0.f;
#pragma unroll
    for (int i = 0; i < 8; i++) {
        float4 w4 = *(const float4*)&wr[lane * 4 + i * 128];
        float4 h4 = *(const float4*)&hs[lane * 4 + i * 128];
        acc += w4.x * h4.x + w4.y * h4.y + w4.z * h4.z + w4.w * h4.w;
    }
#pragma unroll
    for (int o = 16; o; o >>= 1) acc += __shfl_xor_sync(0xffffffffu, acc, o);
    if (lane == 0) out[row] = acc + fcb[row];
}

// ---------------- launch ----------------
extern "C" void kernel_launch(void* const* d_in, const int* in_sizes, int n_in,
                              void* d_out, int out_size) {
    const float* frames = (const float*)d_in[0];
    const float* W_ih   = (const float*)d_in[1];
    const float* W_hh   = (const float*)d_in[2];
    const float* b_ih   = (const float*)d_in[3];
    const float* b_hh   = (const float*)d_in[4];
    const float* fc_w   = (const float*)d_in[5];
    const float* fc_b   = (const float*)d_in[6];
    float* out = (float*)d_out;

    cudaFuncSetAttribute(scan_kernel,
                         cudaFuncAttributeMaxDynamicSharedMemorySize, SCAN_SMEM);

    init_kernel<<<4, 256>>>();

    dim3 g1(GATES / BN, T_STEPS / BM);   // (32, 4) = 128 CTAs
    gemm1_kernel<<<g1, 256>>>(frames, W_ih, b_ih, b_hh);

    scan_kernel<<<SCAN_CTAS, 256, SCAN_SMEM>>>(W_hh);

    final_kernel<<<12288 / 8 / 1, 256>>>(fc_w, fc_b, out);
}

// round 3
// speedup vs baseline: 1.0608x; 1.0608x over previous
#include <cuda_runtime.h>
#include <math.h>

#define T_STEPS 256
#define INPUT   12288
#define HID     1024
#define GATES   4096

// ---------------- device scratch (no allocations allowed) ----------------
__device__ float        g_xproj[T_STEPS * GATES];   // 4 MB
__device__ float        g_h[2][HID];                // ping-pong hidden state
__device__ unsigned int g_bar;                      // monotonic barrier counter

// ---------------- helpers: packed f32x2 FMA ----------------
__device__ __forceinline__ unsigned long long dup2(float x) {
    unsigned long long r;
    asm("mov.b64 %0, {%1, %1};" : "=l"(r) : "f"(x));
    return r;
}
__device__ __forceinline__ void ffma2(unsigned long long& d,
                                      unsigned long long a,
                                      unsigned long long b) {
    asm("fma.rn.f32x2 %0, %1, %2, %0;" : "+l"(d) : "l"(a), "l"(b));
}
__device__ __forceinline__ void unpack2(unsigned long long v, float& lo, float& hi) {
    asm("mov.b64 {%0, %1}, %2;" : "=f"(lo), "=f"(hi) : "l"(v));
}

// ---------------- init: zero h0, reset barrier ----------------
__global__ void init_kernel() {
    int tid = blockIdx.x * blockDim.x + threadIdx.x;
    if (tid < HID) { g_h[0][tid] = 0.f; g_h[1][tid] = 0.f; }
    if (tid == 0) g_bar = 0u;
}

// ---------------- GEMM1: x_proj = frames @ W_ih^T + b_ih + b_hh ----------------
// C[256][4096] = A[256][12288] @ B[4096][12288]^T  (both k-major row-major)
#define BM 64
#define BN 128
#define BK 32
#define NT (INPUT / BK)   // 384 k-tiles

__global__ __launch_bounds__(256, 1)
void gemm1_kernel(const float* __restrict__ A,
                  const float* __restrict__ B,
                  const float* __restrict__ b_ih,
                  const float* __restrict__ b_hh) {
    // double-buffered tiles, conflict-free store mapping
    __shared__ float As[2][BK][BM];   // 2 * 8KB
    __shared__ float Bs[2][BK][BN];   // 2 * 16KB   (total 48KB)

    const int tid = threadIdx.x;
    const int ty  = tid >> 4;    // 0..15 (m)
    const int tx  = tid & 15;    // 0..15 (n)
    const int m0  = blockIdx.y * BM;
    const int n0  = blockIdx.x * BN;

    unsigned long long acc[4][4];
#pragma unroll
    for (int i = 0; i < 4; i++)
#pragma unroll
        for (int j = 0; j < 4; j++) acc[i][j] = 0ULL;

    float4 aReg[2], bReg[4];

    // load-index mapping: within a warp, the quad index kq is FIXED and
    // m/n are 32 consecutive values -> STS banks consecutive -> conflict-free.
    int mA[2], kqA[2], nB[4], kqB[4];
#pragma unroll
    for (int p = 0; p < 2; p++) {
        int idx = p * 256 + tid;
        mA[p] = idx & 63; kqA[p] = idx >> 6;       // 512 float4 of A tile
    }
#pragma unroll
    for (int p = 0; p < 4; p++) {
        int idx = p * 256 + tid;
        nB[p] = idx & 127; kqB[p] = idx >> 7;      // 1024 float4 of B tile
    }

    // ---- prologue: tile 0 ----
#pragma unroll
    for (int p = 0; p < 2; p++)
        aReg[p] = *(const float4*)(A + (size_t)(m0 + mA[p]) * INPUT + kqA[p] * 4);
#pragma unroll
    for (int p = 0; p < 4; p++)
        bReg[p] = *(const float4*)(B + (size_t)(n0 + nB[p]) * INPUT + kqB[p] * 4);
#pragma unroll
    for (int p = 0; p < 2; p++) {
        As[0][kqA[p] * 4 + 0][mA[p]] = aReg[p].x;
        As[0][kqA[p] * 4 + 1][mA[p]] = aReg[p].y;
        As[0][kqA[p] * 4 + 2][mA[p]] = aReg[p].z;
        As[0][kqA[p] * 4 + 3][mA[p]] = aReg[p].w;
    }
#pragma unroll
    for (int p = 0; p < 4; p++) {
        Bs[0][kqB[p] * 4 + 0][nB[p]] = bReg[p].x;
        Bs[0][kqB[p] * 4 + 1][nB[p]] = bReg[p].y;
        Bs[0][kqB[p] * 4 + 2][nB[p]] = bReg[p].z;
        Bs[0][kqB[p] * 4 + 3][nB[p]] = bReg[p].w;
    }
    __syncthreads();

    int buf = 0;
    for (int kt = 0; kt < NT; kt++) {
        if (kt + 1 < NT) {
            int kbase = (kt + 1) * BK;
#pragma unroll
            for (int p = 0; p < 2; p++)
                aReg[p] = *(const float4*)(A + (size_t)(m0 + mA[p]) * INPUT + kbase + kqA[p] * 4);
#pragma unroll
            for (int p = 0; p < 4; p++)
                bReg[p] = *(const float4*)(B + (size_t)(n0 + nB[p]) * INPUT + kbase + kqB[p] * 4);
        }
#pragma unroll
        for (int kk = 0; kk < BK; kk++) {
            float4 a4 = *(const float4*)&As[buf][kk][ty * 4];
            unsigned long long av[4];
            av[0] = dup2(a4.x); av[1] = dup2(a4.y);
            av[2] = dup2(a4.z); av[3] = dup2(a4.w);
            unsigned long long bv[4];
#pragma unroll
            for (int jn = 0; jn < 4; jn++)
                bv[jn] = *(const unsigned long long*)&Bs[buf][kk][tx * 8 + 2 * jn];
#pragma unroll
            for (int i = 0; i < 4; i++)
#pragma unroll
                for (int jn = 0; jn < 4; jn++)
                    ffma2(acc[i][jn], av[i], bv[jn]);
        }
        if (kt + 1 < NT) {
            int nb = buf ^ 1;
#pragma unroll
            for (int p = 0; p < 2; p++) {
                As[nb][kqA[p] * 4 + 0][mA[p]] = aReg[p].x;
                As[nb][kqA[p] * 4 + 1][mA[p]] = aReg[p].y;
                As[nb][kqA[p] * 4 + 2][mA[p]] = aReg[p].z;
                As[nb][kqA[p] * 4 + 3][mA[p]] = aReg[p].w;
            }
#pragma unroll
            for (int p = 0; p < 4; p++) {
                Bs[nb][kqB[p] * 4 + 0][nB[p]] = bReg[p].x;
                Bs[nb][kqB[p] * 4 + 1][nB[p]] = bReg[p].y;
                Bs[nb][kqB[p] * 4 + 2][nB[p]] = bReg[p].z;
                Bs[nb][kqB[p] * 4 + 3][nB[p]] = bReg[p].w;
            }
            __syncthreads();
            buf = nb;
        }
    }

    // epilogue: add biases, store
#pragma unroll
    for (int i = 0; i < 4; i++) {
        int m = m0 + ty * 4 + i;
        float* crow = g_xproj + (size_t)m * GATES;
#pragma unroll
        for (int jn = 0; jn < 4; jn++) {
            int n = n0 + tx * 8 + 2 * jn;
            float lo, hi;
            unpack2(acc[i][jn], lo, hi);
            float2 v;
            v.x = lo + b_ih[n]     + b_hh[n];
            v.y = hi + b_ih[n + 1] + b_hh[n + 1];
            *(float2*)&crow[n] = v;
        }
    }
}

// ---------------- persistent LSTM scan (W_hh fully in registers) ----------------
// 128 CTAs x 256 threads. CTA b owns hidden units [8b, 8b+8); warp w <-> unit 8b+w.
// Each lane holds its 4x32 W_hh fragment in registers (128 floats = 64 f32x2 regs).
#define SCAN_CTAS 128

__device__ __forceinline__ float fast_sigmoid(float x) {
    return __fdividef(1.f, 1.f + __expf(-x));
}
__device__ __forceinline__ float fast_tanh(float x) {
    float e = __expf(-2.f * x);
    return __fdividef(1.f - e, 1.f + e);
}

__global__ __launch_bounds__(256, 1)
void scan_kernel(const float* __restrict__ Whh) {
    __shared__ float hs[HID];

    const int tid  = threadIdx.x;
    const int warp = tid >> 5;
    const int lane = tid & 31;
    const int b    = blockIdx.x;
    const int j    = b * 8 + warp;   // this warp's hidden unit

    // W fragment in registers: gate g, chunk i -> floats [lane*4 + i*128, +4)
    unsigned long long wreg[4][8][2];
#pragma unroll
    for (int g = 0; g < 4; g++) {
        const float* wrow = Whh + (size_t)(g * HID + j) * HID;
#pragma unroll
        for (int i = 0; i < 8; i++) {
            ulonglong2 v = *(const ulonglong2*)&wrow[lane * 4 + i * 128];
            wreg[g][i][0] = v.x;
            wreg[g][i][1] = v.y;
        }
    }

    float cstate = 0.f;

    for (int t = 0; t < T_STEPS; t++) {
        const float* hin  = g_h[t & 1];
        float*       hout = g_h[(t + 1) & 1];

        // x_proj contributions (independent of h; L1-safe: written by prior kernel)
        float xg0 = __ldg(&g_xproj[(size_t)t * GATES + 0 * HID + j]);
        float xg1 = __ldg(&g_xproj[(size_t)t * GATES + 1 * HID + j]);
        float xg2 = __ldg(&g_xproj[(size_t)t * GATES + 2 * HID + j]);
        float xg3 = __ldg(&g_xproj[(size_t)t * GATES + 3 * HID + j]);

        // stage h into smem (L2-coherent read, bypass L1)
        float4 hv = __ldcg((const float4*)(hin + tid * 4));
        *(float4*)&hs[tid * 4] = hv;
        __syncthreads();

        unsigned long long acc[4] = {0ULL, 0ULL, 0ULL, 0ULL};
#pragma unroll
        for (int i = 0; i < 8; i++) {
            ulonglong2 h2 = *(const ulonglong2*)&hs[lane * 4 + i * 128];
#pragma unroll
            for (int g = 0; g < 4; g++) {
                ffma2(acc[g], h2.x, wreg[g][i][0]);
                ffma2(acc[g], h2.y, wreg[g][i][1]);
            }
        }
        float red[4];
#pragma unroll
        for (int g = 0; g < 4; g++) {
            float lo, hi;
            unpack2(acc[g], lo, hi);
            red[g] = lo + hi;
        }
#pragma unroll
        for (int o = 16; o; o >>= 1) {
#pragma unroll
            for (int g = 0; g < 4; g++)
                red[g] += __shfl_xor_sync(0xffffffffu, red[g], o);
        }

        float gi = fast_sigmoid(xg0 + red[0]);
        float gf = fast_sigmoid(xg1 + red[1]);
        float gg = fast_tanh(xg2 + red[2]);
        float go = fast_sigmoid(xg3 + red[3]);
        cstate = gf * cstate + gi * gg;
        float hnew = go * fast_tanh(cstate);

        if (lane == 0) __stcg(&hout[j], hnew);

        // ---- global barrier: release arrive + acquire spin ----
        __threadfence();
        __syncthreads();   // all warps stored + fenced; also guards hs reuse
        if (tid == 0) {
            asm volatile("red.release.gpu.global.add.u32 [%0], 1;"
                         :: "l"(&g_bar) : "memory");
            unsigned int target = (unsigned int)SCAN_CTAS * (unsigned int)(t + 1);
            unsigned int v;
            do {
                asm volatile("ld.acquire.gpu.global.u32 %0, [%1];"
                             : "=r"(v) : "l"(&g_bar));
            } while (v < target);
        }
        __syncthreads();
    }
}

// ---------------- final: out = h_T @ fc_w^T + fc_b ----------------
// 2 rows per warp -> 16 independent LDG.128 in flight per lane
__global__ __launch_bounds__(256, 2)
void final_kernel(const float* __restrict__ fcw,
                  const float* __restrict__ fcb,
                  float* __restrict__ out) {
    __shared__ float hs[HID];
    const int tid = threadIdx.x, warp = tid >> 5, lane = tid & 31;
    // h_T lives in g_h[0] (t=255 writes buffer (255+1)&1 = 0)
    *(float4*)&hs[tid * 4] = __ldcg((const float4*)(g_h[0] + tid * 4));
    __syncthreads();

    int row = blockIdx.x * 16 + warp * 2;   // 768 blocks * 8 warps * 2 rows
    const float* wr0 = fcw + (size_t)row * HID;
    const float* wr1 = wr0 + HID;
    float acc0 = 0.f, acc1 = 0.f;
#pragma unroll
    for (int i = 0; i < 8; i++) {
        float4 h4 = *(const float4*)&hs[lane * 4 + i * 128];
        float4 a4 = *(const float4*)&wr0[lane * 4 + i * 128];
        float4 b4 = *(const float4*)&wr1[lane * 4 + i * 128];
        acc0 += a4.x * h4.x + a4.y * h4.y + a4.z * h4.z + a4.w * h4.w;
        acc1 += b4.x * h4.x + b4.y * h4.y + b4.z * h4.z + b4.w * h4.w;
    }
#pragma unroll
    for (int o = 16; o; o >>= 1) {
        acc0 += __shfl_xor_sync(0xffffffffu, acc0, o);
        acc1 += __shfl_xor_sync(0xffffffffu, acc1, o);
    }
    if (lane == 0) {
        out[row]     = acc0 + fcb[row];
        out[row + 1] = acc1 + fcb[row + 1];
    }
}

// ---------------- launch ----------------
extern "C" void kernel_launch(void* const* d_in, const int* in_sizes, int n_in,
                              void* d_out, int out_size) {
    const float* frames = (const float*)d_in[0];
    const float* W_ih   = (const float*)d_in[1];
    const float* W_hh   = (const float*)d_in[2];
    const float* b_ih   = (const float*)d_in[3];
    const float* b_hh   = (const float*)d_in[4];
    const float* fc_w   = (const float*)d_in[5];
    const float* fc_b   = (const float*)d_in[6];
    float* out = (float*)d_out;

    init_kernel<<<4, 256>>>();

    dim3 g1(GATES / BN, T_STEPS / BM);   // (32, 4) = 128 CTAs
    gemm1_kernel<<<g1, 256>>>(frames, W_ih, b_ih, b_hh);

    scan_kernel<<<SCAN_CTAS, 256>>>(W_hh);

    final_kernel<<<12288 / 16, 256>>>(fc_w, fc_b, out);
}

// round 4
// speedup vs baseline: 1.1448x; 1.0792x over previous
#include <cuda_runtime.h>
#include <math.h>

#define T_STEPS 256
#define INPUT   12288
#define HID     1024
#define GATES   4096

// ---------------- device scratch (no allocations allowed) ----------------
__device__ float              g_xproj[T_STEPS * GATES];  // 4 MB
// hidden state published as {epoch:32 | float_bits:32}, ping-pong by t parity
__device__ unsigned long long g_hp[2][HID];

// ---------------- helpers: packed f32x2 FMA ----------------
__device__ __forceinline__ unsigned long long dup2(float x) {
    unsigned long long r;
    asm("mov.b64 %0, {%1, %1};" : "=l"(r) : "f"(x));
    return r;
}
__device__ __forceinline__ void ffma2(unsigned long long& d,
                                      unsigned long long a,
                                      unsigned long long b) {
    asm("fma.rn.f32x2 %0, %1, %2, %0;" : "+l"(d) : "l"(a), "l"(b));
}
__device__ __forceinline__ void unpack2(unsigned long long v, float& lo, float& hi) {
    asm("mov.b64 {%0, %1}, %2;" : "=f"(lo), "=f"(hi) : "l"(v));
}

// ---------------- init: h_0 = 0 with epoch 0 in both buffers ----------------
__global__ void init_kernel() {
    int tid = blockIdx.x * blockDim.x + threadIdx.x;
    if (tid < HID) {
        g_hp[0][tid] = 0ULL;   // epoch 0, h = 0.0f
        g_hp[1][tid] = 0ULL;
    }
}

// ---------------- GEMM1: x_proj = frames @ W_ih^T + b_ih + b_hh ----------------
#define BM 64
#define BN 128
#define BK 32
#define NT (INPUT / BK)   // 384 k-tiles

__global__ __launch_bounds__(256, 1)
void gemm1_kernel(const float* __restrict__ A,
                  const float* __restrict__ B,
                  const float* __restrict__ b_ih,
                  const float* __restrict__ b_hh) {
    __shared__ float As[2][BK][BM];
    __shared__ float Bs[2][BK][BN];

    const int tid = threadIdx.x;
    const int ty  = tid >> 4;
    const int tx  = tid & 15;
    const int m0  = blockIdx.y * BM;
    const int n0  = blockIdx.x * BN;

    unsigned long long acc[4][4];
#pragma unroll
    for (int i = 0; i < 4; i++)
#pragma unroll
        for (int j = 0; j < 4; j++) acc[i][j] = 0ULL;

    float4 aReg[2], bReg[4];
    int mA[2], kqA[2], nB[4], kqB[4];
#pragma unroll
    for (int p = 0; p < 2; p++) {
        int idx = p * 256 + tid;
        mA[p] = idx & 63; kqA[p] = idx >> 6;
    }
#pragma unroll
    for (int p = 0; p < 4; p++) {
        int idx = p * 256 + tid;
        nB[p] = idx & 127; kqB[p] = idx >> 7;
    }

#pragma unroll
    for (int p = 0; p < 2; p++)
        aReg[p] = *(const float4*)(A + (size_t)(m0 + mA[p]) * INPUT + kqA[p] * 4);
#pragma unroll
    for (int p = 0; p < 4; p++)
        bReg[p] = *(const float4*)(B + (size_t)(n0 + nB[p]) * INPUT + kqB[p] * 4);
#pragma unroll
    for (int p = 0; p < 2; p++) {
        As[0][kqA[p] * 4 + 0][mA[p]] = aReg[p].x;
        As[0][kqA[p] * 4 + 1][mA[p]] = aReg[p].y;
        As[0][kqA[p] * 4 + 2][mA[p]] = aReg[p].z;
        As[0][kqA[p] * 4 + 3][mA[p]] = aReg[p].w;
    }
#pragma unroll
    for (int p = 0; p < 4; p++) {
        Bs[0][kqB[p] * 4 + 0][nB[p]] = bReg[p].x;
        Bs[0][kqB[p] * 4 + 1][nB[p]] = bReg[p].y;
        Bs[0][kqB[p] * 4 + 2][nB[p]] = bReg[p].z;
        Bs[0][kqB[p] * 4 + 3][nB[p]] = bReg[p].w;
    }
    __syncthreads();

    int buf = 0;
    for (int kt = 0; kt < NT; kt++) {
        if (kt + 1 < NT) {
            int kbase = (kt + 1) * BK;
#pragma unroll
            for (int p = 0; p < 2; p++)
                aReg[p] = *(const float4*)(A + (size_t)(m0 + mA[p]) * INPUT + kbase + kqA[p] * 4);
#pragma unroll
            for (int p = 0; p < 4; p++)
                bReg[p] = *(const float4*)(B + (size_t)(n0 + nB[p]) * INPUT + kbase + kqB[p] * 4);
        }
#pragma unroll
        for (int kk = 0; kk < BK; kk++) {
            float4 a4 = *(const float4*)&As[buf][kk][ty * 4];
            unsigned long long av[4];
            av[0] = dup2(a4.x); av[1] = dup2(a4.y);
            av[2] = dup2(a4.z); av[3] = dup2(a4.w);
            unsigned long long bv[4];
#pragma unroll
            for (int jn = 0; jn < 4; jn++)
                bv[jn] = *(const unsigned long long*)&Bs[buf][kk][tx * 8 + 2 * jn];
#pragma unroll
            for (int i = 0; i < 4; i++)
#pragma unroll
                for (int jn = 0; jn < 4; jn++)
                    ffma2(acc[i][jn], av[i], bv[jn]);
        }
        if (kt + 1 < NT) {
            int nb = buf ^ 1;
#pragma unroll
            for (int p = 0; p < 2; p++) {
                As[nb][kqA[p] * 4 + 0][mA[p]] = aReg[p].x;
                As[nb][kqA[p] * 4 + 1][mA[p]] = aReg[p].y;
                As[nb][kqA[p] * 4 + 2][mA[p]] = aReg[p].z;
                As[nb][kqA[p] * 4 + 3][mA[p]] = aReg[p].w;
            }
#pragma unroll
            for (int p = 0; p < 4; p++) {
                Bs[nb][kqB[p] * 4 + 0][nB[p]] = bReg[p].x;
                Bs[nb][kqB[p] * 4 + 1][nB[p]] = bReg[p].y;
                Bs[nb][kqB[p] * 4 + 2][nB[p]] = bReg[p].z;
                Bs[nb][kqB[p] * 4 + 3][nB[p]] = bReg[p].w;
            }
            __syncthreads();
            buf = nb;
        }
    }

#pragma unroll
    for (int i = 0; i < 4; i++) {
        int m = m0 + ty * 4 + i;
        float* crow = g_xproj + (size_t)m * GATES;
#pragma unroll
        for (int jn = 0; jn < 4; jn++) {
            int n = n0 + tx * 8 + 2 * jn;
            float lo, hi;
            unpack2(acc[i][jn], lo, hi);
            float2 v;
            v.x = lo + b_ih[n]     + b_hh[n];
            v.y = hi + b_ih[n + 1] + b_hh[n + 1];
            *(float2*)&crow[n] = v;
        }
    }
}

// ---------------- persistent LSTM scan: payload-epoch synchronization ----------------
// 128 CTAs x 256 threads. CTA b owns hidden units [8b, 8b+8); warp w <-> unit 8b+w.
// Each lane holds its 4x(4 floats x 8 chunks) W_hh fragment in registers.
// h_t is published as {epoch=t | bits(h)} u64 into g_hp[t&1]; consumers spin on
// exactly their own 4 words. No atomics, no fences, no global counter.
#define SCAN_CTAS 128

__device__ __forceinline__ float fast_sigmoid(float x) {
    return __fdividef(1.f, 1.f + __expf(-x));
}
__device__ __forceinline__ float fast_tanh(float x) {
    float e = __expf(-2.f * x);
    return __fdividef(1.f - e, 1.f + e);
}
__device__ __forceinline__ unsigned long long ld_rlx(const unsigned long long* p) {
    unsigned long long v;
    asm volatile("ld.relaxed.gpu.global.u64 %0, [%1];" : "=l"(v) : "l"(p) : "memory");
    return v;
}
__device__ __forceinline__ void st_rlx(unsigned long long* p, unsigned long long v) {
    asm volatile("st.relaxed.gpu.global.u64 [%0], %1;" :: "l"(p), "l"(v) : "memory");
}

__global__ __launch_bounds__(256, 1)
void scan_kernel(const float* __restrict__ Whh) {
    __shared__ float hs[HID];

    const int tid  = threadIdx.x;
    const int warp = tid >> 5;
    const int lane = tid & 31;
    const int b    = blockIdx.x;
    const int j    = b * 8 + warp;   // this warp's hidden unit

    // W fragment in registers: gate g, chunk i -> floats [lane*4 + i*128, +4)
    unsigned long long wreg[4][8][2];
#pragma unroll
    for (int g = 0; g < 4; g++) {
        const float* wrow = Whh + (size_t)(g * HID + j) * HID;
#pragma unroll
        for (int i = 0; i < 8; i++) {
            ulonglong2 v = *(const ulonglong2*)&wrow[lane * 4 + i * 128];
            wreg[g][i][0] = v.x;
            wreg[g][i][1] = v.y;
        }
    }

    float cstate = 0.f;

    for (int t = 0; t < T_STEPS; t++) {
        // prefetch this step's x_proj gates (independent of h)
        float xg0 = __ldg(&g_xproj[(size_t)t * GATES + 0 * HID + j]);
        float xg1 = __ldg(&g_xproj[(size_t)t * GATES + 1 * HID + j]);
        float xg2 = __ldg(&g_xproj[(size_t)t * GATES + 2 * HID + j]);
        float xg3 = __ldg(&g_xproj[(size_t)t * GATES + 3 * HID + j]);

        // ---- acquire h_t: spin until our 4 payload epochs == t, drop into smem ----
        const unsigned long long* hb = g_hp[t & 1];
        const unsigned int want = (unsigned int)t;
#pragma unroll
        for (int q = 0; q < 4; q++) {
            const unsigned long long* p = hb + tid + q * 256;
            unsigned long long v = ld_rlx(p);
            while ((unsigned int)(v >> 32) != want) v = ld_rlx(p);
            hs[tid + q * 256] = __uint_as_float((unsigned int)v);
        }
        __syncthreads();

        // ---- gate matvec (W in regs, h in smem) ----
        unsigned long long acc[4] = {0ULL, 0ULL, 0ULL, 0ULL};
#pragma unroll
        for (int i = 0; i < 8; i++) {
            ulonglong2 h2 = *(const ulonglong2*)&hs[lane * 4 + i * 128];
#pragma unroll
            for (int g = 0; g < 4; g++) {
                ffma2(acc[g], h2.x, wreg[g][i][0]);
                ffma2(acc[g], h2.y, wreg[g][i][1]);
            }
        }
        __syncthreads();   // all hs reads done; next iteration may overwrite hs

        float red[4];
#pragma unroll
        for (int g = 0; g < 4; g++) {
            float lo, hi;
            unpack2(acc[g], lo, hi);
            red[g] = lo + hi;
        }
#pragma unroll
        for (int o = 16; o; o >>= 1) {
#pragma unroll
            for (int g = 0; g < 4; g++)
                red[g] += __shfl_xor_sync(0xffffffffu, red[g], o);
        }

        float gi = fast_sigmoid(xg0 + red[0]);
        float gf = fast_sigmoid(xg1 + red[1]);
        float gg = fast_tanh(xg2 + red[2]);
        float go = fast_sigmoid(xg3 + red[3]);
        cstate = gf * cstate + gi * gg;
        float hnew = go * fast_tanh(cstate);

        // ---- publish h_{t+1} = {epoch t+1 | bits} ----
        if (lane == 0) {
            unsigned long long pk =
                ((unsigned long long)(unsigned int)(t + 1) << 32) |
                (unsigned long long)__float_as_uint(hnew);
            st_rlx(&g_hp[(t + 1) & 1][j], pk);
        }
    }
}

// ---------------- final: out = h_T @ fc_w^T + fc_b ----------------
__global__ __launch_bounds__(256, 2)
void final_kernel(const float* __restrict__ fcw,
                  const float* __restrict__ fcb,
                  float* __restrict__ out) {
    __shared__ float hs[HID];
    const int tid = threadIdx.x, warp = tid >> 5, lane = tid & 31;
    // h_T (epoch 256) lives in g_hp[0]; kernel boundary guarantees visibility
#pragma unroll
    for (int q = 0; q < 4; q++)
        hs[tid + q * 256] = __uint_as_float((unsigned int)g_hp[0][tid + q * 256]);
    __syncthreads();

    int row = blockIdx.x * 16 + warp * 2;
    const float* wr0 = fcw + (size_t)row * HID;
    const float* wr1 = wr0 + HID;
    float acc0 = 0.f, acc1 = 0.f;
#pragma unroll
    for (int i = 0; i < 8; i++) {
        float4 h4 = *(const float4*)&hs[lane * 4 + i * 128];
        float4 a4 = *(const float4*)&wr0[lane * 4 + i * 128];
        float4 b4 = *(const float4*)&wr1[lane * 4 + i * 128];
        acc0 += a4.x * h4.x + a4.y * h4.y + a4.z * h4.z + a4.w * h4.w;
        acc1 += b4.x * h4.x + b4.y * h4.y + b4.z * h4.z + b4.w * h4.w;
    }
#pragma unroll
    for (int o = 16; o; o >>= 1) {
        acc0 += __shfl_xor_sync(0xffffffffu, acc0, o);
        acc1 += __shfl_xor_sync(0xffffffffu, acc1, o);
    }
    if (lane == 0) {
        out[row]     = acc0 + fcb[row];
        out[row + 1] = acc1 + fcb[row + 1];
    }
}

// ---------------- launch ----------------
extern "C" void kernel_launch(void* const* d_in, const int* in_sizes, int n_in,
                              void* d_out, int out_size) {
    const float* frames = (const float*)d_in[0];
    const float* W_ih   = (const float*)d_in[1];
    const float* W_hh   = (const float*)d_in[2];
    const float* b_ih   = (const float*)d_in[3];
    const float* b_hh   = (const float*)d_in[4];
    const float* fc_w   = (const float*)d_in[5];
    const float* fc_b   = (const float*)d_in[6];
    float* out = (float*)d_out;

    init_kernel<<<4, 256>>>();

    dim3 g1(GATES / BN, T_STEPS / BM);   // (32, 4) = 128 CTAs
    gemm1_kernel<<<g1, 256>>>(frames, W_ih, b_ih, b_hh);

    scan_kernel<<<SCAN_CTAS, 256>>>(W_hh);

    final_kernel<<<12288 / 16, 256>>>(fc_w, fc_b, out);
}

// round 5
// speedup vs baseline: 1.4505x; 1.2670x over previous
#include <cuda_runtime.h>
#include <math.h>

#define T_STEPS 256
#define INPUT   12288
#define HID     1024
#define GATES   4096

// ---------------- device scratch (no allocations allowed) ----------------
__device__ float              g_xproj[T_STEPS * GATES];  // 4 MB
// hidden state published as {epoch:32 | float_bits:32}, ping-pong by t parity
__device__ unsigned long long g_hp[2][HID];

// ---------------- helpers: packed f32x2 FMA ----------------
__device__ __forceinline__ unsigned long long dup2(float x) {
    unsigned long long r;
    asm("mov.b64 %0, {%1, %1};" : "=l"(r) : "f"(x));
    return r;
}
__device__ __forceinline__ void ffma2(unsigned long long& d,
                                      unsigned long long a,
                                      unsigned long long b) {
    asm("fma.rn.f32x2 %0, %1, %2, %0;" : "+l"(d) : "l"(a), "l"(b));
}
__device__ __forceinline__ void unpack2(unsigned long long v, float& lo, float& hi) {
    asm("mov.b64 {%0, %1}, %2;" : "=f"(lo), "=f"(hi) : "l"(v));
}

// ---------------- init: h_0 = 0 with epoch 0 in both buffers ----------------
__global__ void init_kernel() {
    int tid = blockIdx.x * blockDim.x + threadIdx.x;
    if (tid < HID) {
        g_hp[0][tid] = 0ULL;   // epoch 0, h = 0.0f
        g_hp[1][tid] = 0ULL;
    }
}

// ---------------- GEMM1: x_proj = frames @ W_ih^T + b_ih + b_hh ----------------
// C[256][4096] = A[256][12288] @ B[4096][12288]^T
// Thread tile: 4m x 8n, with n as two contiguous float4 groups
// (n = n0+tx*4+{0..3} and n = n0+64+tx*4+{0..3}) -> all LDS are .128 conflict-free.
#define BM 64
#define BN 128
#define BK 32
#define NT (INPUT / BK)   // 384 k-tiles

__global__ __launch_bounds__(256, 1)
void gemm1_kernel(const float* __restrict__ A,
                  const float* __restrict__ B,
                  const float* __restrict__ b_ih,
                  const float* __restrict__ b_hh) {
    __shared__ float As[2][BK][BM];   // rows 256B -> bank-0 aligned
    __shared__ float Bs[2][BK][BN];   // rows 512B -> bank-0 aligned

    const int tid = threadIdx.x;
    const int ty  = tid >> 4;    // 0..15 (m group)
    const int tx  = tid & 15;    // 0..15 (n group)
    const int m0  = blockIdx.y * BM;
    const int n0  = blockIdx.x * BN;

    unsigned long long acc[4][4];   // [i][0..1] for n-group0, [i][2..3] for n-group1
#pragma unroll
    for (int i = 0; i < 4; i++)
#pragma unroll
        for (int j = 0; j < 4; j++) acc[i][j] = 0ULL;

    float4 aReg[2], bReg[4];
    int mA[2], kqA[2], nB[4], kqB[4];
#pragma unroll
    for (int p = 0; p < 2; p++) {
        int idx = p * 256 + tid;
        mA[p] = idx & 63; kqA[p] = idx >> 6;
    }
#pragma unroll
    for (int p = 0; p < 4; p++) {
        int idx = p * 256 + tid;
        nB[p] = idx & 127; kqB[p] = idx >> 7;
    }

    // ---- prologue: tile 0 ----
#pragma unroll
    for (int p = 0; p < 2; p++)
        aReg[p] = *(const float4*)(A + (size_t)(m0 + mA[p]) * INPUT + kqA[p] * 4);
#pragma unroll
    for (int p = 0; p < 4; p++)
        bReg[p] = *(const float4*)(B + (size_t)(n0 + nB[p]) * INPUT + kqB[p] * 4);
#pragma unroll
    for (int p = 0; p < 2; p++) {
        As[0][kqA[p] * 4 + 0][mA[p]] = aReg[p].x;
        As[0][kqA[p] * 4 + 1][mA[p]] = aReg[p].y;
        As[0][kqA[p] * 4 + 2][mA[p]] = aReg[p].z;
        As[0][kqA[p] * 4 + 3][mA[p]] = aReg[p].w;
    }
#pragma unroll
    for (int p = 0; p < 4; p++) {
        Bs[0][kqB[p] * 4 + 0][nB[p]] = bReg[p].x;
        Bs[0][kqB[p] * 4 + 1][nB[p]] = bReg[p].y;
        Bs[0][kqB[p] * 4 + 2][nB[p]] = bReg[p].z;
        Bs[0][kqB[p] * 4 + 3][nB[p]] = bReg[p].w;
    }
    __syncthreads();

    int buf = 0;
    for (int kt = 0; kt < NT; kt++) {
        if (kt + 1 < NT) {
            int kbase = (kt + 1) * BK;
#pragma unroll
            for (int p = 0; p < 2; p++)
                aReg[p] = *(const float4*)(A + (size_t)(m0 + mA[p]) * INPUT + kbase + kqA[p] * 4);
#pragma unroll
            for (int p = 0; p < 4; p++)
                bReg[p] = *(const float4*)(B + (size_t)(n0 + nB[p]) * INPUT + kbase + kqB[p] * 4);
        }
#pragma unroll
        for (int kk = 0; kk < BK; kk++) {
            // A fragment: broadcast LDS.128
            float4 a4 = *(const float4*)&As[buf][kk][ty * 4];
            unsigned long long av[4];
            av[0] = dup2(a4.x); av[1] = dup2(a4.y);
            av[2] = dup2(a4.z); av[3] = dup2(a4.w);
            // B fragments: two conflict-free LDS.128, bitcast to f32x2 pairs
            ulonglong2 bv0 = *(const ulonglong2*)&Bs[buf][kk][tx * 4];
            ulonglong2 bv1 = *(const ulonglong2*)&Bs[buf][kk][64 + tx * 4];
#pragma unroll
            for (int i = 0; i < 4; i++) {
                ffma2(acc[i][0], av[i], bv0.x);
                ffma2(acc[i][1], av[i], bv0.y);
                ffma2(acc[i][2], av[i], bv1.x);
                ffma2(acc[i][3], av[i], bv1.y);
            }
        }
        if (kt + 1 < NT) {
            int nb = buf ^ 1;
#pragma unroll
            for (int p = 0; p < 2; p++) {
                As[nb][kqA[p] * 4 + 0][mA[p]] = aReg[p].x;
                As[nb][kqA[p] * 4 + 1][mA[p]] = aReg[p].y;
                As[nb][kqA[p] * 4 + 2][mA[p]] = aReg[p].z;
                As[nb][kqA[p] * 4 + 3][mA[p]] = aReg[p].w;
            }
#pragma unroll
            for (int p = 0; p < 4; p++) {
                Bs[nb][kqB[p] * 4 + 0][nB[p]] = bReg[p].x;
                Bs[nb][kqB[p] * 4 + 1][nB[p]] = bReg[p].y;
                Bs[nb][kqB[p] * 4 + 2][nB[p]] = bReg[p].z;
                Bs[nb][kqB[p] * 4 + 3][nB[p]] = bReg[p].w;
            }
            __syncthreads();
            buf = nb;
        }
    }

    // epilogue: add biases, store two float4 per row
    const int n1 = n0 + tx * 4;
    const int n2 = n0 + 64 + tx * 4;
    float4 bi1 = *(const float4*)&b_ih[n1];
    float4 bh1 = *(const float4*)&b_hh[n1];
    float4 bi2 = *(const float4*)&b_ih[n2];
    float4 bh2 = *(const float4*)&b_hh[n2];
#pragma unroll
    for (int i = 0; i < 4; i++) {
        int m = m0 + ty * 4 + i;
        float* crow = g_xproj + (size_t)m * GATES;
        float l0, h0, l1, h1;
        unpack2(acc[i][0], l0, h0);
        unpack2(acc[i][1], l1, h1);
        float4 v1 = make_float4(l0 + bi1.x + bh1.x, h0 + bi1.y + bh1.y,
                                l1 + bi1.z + bh1.z, h1 + bi1.w + bh1.w);
        *(float4*)&crow[n1] = v1;
        unpack2(acc[i][2], l0, h0);
        unpack2(acc[i][3], l1, h1);
        float4 v2 = make_float4(l0 + bi2.x + bh2.x, h0 + bi2.y + bh2.y,
                                l1 + bi2.z + bh2.z, h1 + bi2.w + bh2.w);
        *(float4*)&crow[n2] = v2;
    }
}

// ---------------- persistent LSTM scan: payload-epoch synchronization ----------------
#define SCAN_CTAS 128

__device__ __forceinline__ float fast_sigmoid(float x) {
    return __fdividef(1.f, 1.f + __expf(-x));
}
__device__ __forceinline__ float fast_tanh(float x) {
    float e = __expf(-2.f * x);
    return __fdividef(1.f - e, 1.f + e);
}
__device__ __forceinline__ unsigned long long ld_rlx(const unsigned long long* p) {
    unsigned long long v;
    asm volatile("ld.relaxed.gpu.global.u64 %0, [%1];" : "=l"(v) : "l"(p) : "memory");
    return v;
}
__device__ __forceinline__ void st_rlx(unsigned long long* p, unsigned long long v) {
    asm volatile("st.relaxed.gpu.global.u64 [%0], %1;" :: "l"(p), "l"(v) : "memory");
}

__global__ __launch_bounds__(256, 1)
void scan_kernel(const float* __restrict__ Whh) {
    __shared__ float hs[2][HID];   // double-buffered: one barrier per step

    const int tid  = threadIdx.x;
    const int warp = tid >> 5;
    const int lane = tid & 31;
    const int b    = blockIdx.x;
    const int j    = b * 8 + warp;   // this warp's hidden unit

    // W fragment in registers: gate g, chunk i -> floats [lane*4 + i*128, +4)
    unsigned long long wreg[4][8][2];
#pragma unroll
    for (int g = 0; g < 4; g++) {
        const float* wrow = Whh + (size_t)(g * HID + j) * HID;
#pragma unroll
        for (int i = 0; i < 8; i++) {
            ulonglong2 v = *(const ulonglong2*)&wrow[lane * 4 + i * 128];
            wreg[g][i][0] = v.x;
            wreg[g][i][1] = v.y;
        }
    }

    float cstate = 0.f;

    for (int t = 0; t < T_STEPS; t++) {
        // prefetch this step's x_proj gates (independent of h)
        float xg0 = __ldg(&g_xproj[(size_t)t * GATES + 0 * HID + j]);
        float xg1 = __ldg(&g_xproj[(size_t)t * GATES + 1 * HID + j]);
        float xg2 = __ldg(&g_xproj[(size_t)t * GATES + 2 * HID + j]);
        float xg3 = __ldg(&g_xproj[(size_t)t * GATES + 3 * HID + j]);

        // ---- acquire h_t: parallel poll on our 4 payload words ----
        const unsigned long long* p0 = g_hp[t & 1] + tid;
        const unsigned int want = (unsigned int)t;
        unsigned long long v0, v1, v2, v3;
        bool ok;
        do {
            v0 = ld_rlx(p0);
            v1 = ld_rlx(p0 + 256);
            v2 = ld_rlx(p0 + 512);
            v3 = ld_rlx(p0 + 768);
            ok = ((unsigned int)(v0 >> 32) == want) &
                 ((unsigned int)(v1 >> 32) == want) &
                 ((unsigned int)(v2 >> 32) == want) &
                 ((unsigned int)(v3 >> 32) == want);
        } while (!ok);
        float* cur = hs[t & 1];
        cur[tid]       = __uint_as_float((unsigned int)v0);
        cur[tid + 256] = __uint_as_float((unsigned int)v1);
        cur[tid + 512] = __uint_as_float((unsigned int)v2);
        cur[tid + 768] = __uint_as_float((unsigned int)v3);
        __syncthreads();

        // ---- gate matvec (W in regs, h in smem) ----
        unsigned long long acc[4] = {0ULL, 0ULL, 0ULL, 0ULL};
#pragma unroll
        for (int i = 0; i < 8; i++) {
            ulonglong2 h2 = *(const ulonglong2*)&cur[lane * 4 + i * 128];
#pragma unroll
            for (int g = 0; g < 4; g++) {
                ffma2(acc[g], h2.x, wreg[g][i][0]);
                ffma2(acc[g], h2.y, wreg[g][i][1]);
            }
        }

        float red[4];
#pragma unroll
        for (int g = 0; g < 4; g++) {
            float lo, hi;
            unpack2(acc[g], lo, hi);
            red[g] = lo + hi;
        }
#pragma unroll
        for (int o = 16; o; o >>= 1) {
#pragma unroll
            for (int g = 0; g < 4; g++)
                red[g] += __shfl_xor_sync(0xffffffffu, red[g], o);
        }

        float gi = fast_sigmoid(xg0 + red[0]);
        float gf = fast_sigmoid(xg1 + red[1]);
        float gg = fast_tanh(xg2 + red[2]);
        float go = fast_sigmoid(xg3 + red[3]);
        cstate = gf * cstate + gi * gg;
        float hnew = go * fast_tanh(cstate);

        // ---- publish h_{t+1} = {epoch t+1 | bits} ----
        if (lane == 0) {
            unsigned long long pk =
                ((unsigned long long)(unsigned int)(t + 1) << 32) |
                (unsigned long long)__float_as_uint(hnew);
            st_rlx(&g_hp[(t + 1) & 1][j], pk);
        }
    }
}

// ---------------- final: out = h_T @ fc_w^T + fc_b ----------------
__global__ __launch_bounds__(256, 2)
void final_kernel(const float* __restrict__ fcw,
                  const float* __restrict__ fcb,
                  float* __restrict__ out) {
    __shared__ float hs[HID];
    const int tid = threadIdx.x, warp = tid >> 5, lane = tid & 31;
#pragma unroll
    for (int q = 0; q < 4; q++)
        hs[tid + q * 256] = __uint_as_float((unsigned int)g_hp[0][tid + q * 256]);
    __syncthreads();

    int row = blockIdx.x * 16 + warp * 2;
    const float* wr0 = fcw + (size_t)row * HID;
    const float* wr1 = wr0 + HID;
    float acc0 = 0.f, acc1 = 0.f;
#pragma unroll
    for (int i = 0; i < 8; i++) {
        float4 h4 = *(const float4*)&hs[lane * 4 + i * 128];
        float4 a4 = *(const float4*)&wr0[lane * 4 + i * 128];
        float4 b4 = *(const float4*)&wr1[lane * 4 + i * 128];
        acc0 += a4.x * h4.x + a4.y * h4.y + a4.z * h4.z + a4.w * h4.w;
        acc1 += b4.x * h4.x + b4.y * h4.y + b4.z * h4.z + b4.w * h4.w;
    }
#pragma unroll
    for (int o = 16; o; o >>= 1) {
        acc0 += __shfl_xor_sync(0xffffffffu, acc0, o);
        acc1 += __shfl_xor_sync(0xffffffffu, acc1, o);
    }
    if (lane == 0) {
        out[row]     = acc0 + fcb[row];
        out[row + 1] = acc1 + fcb[row + 1];
    }
}

// ---------------- launch ----------------
extern "C" void kernel_launch(void* const* d_in, const int* in_sizes, int n_in,
                              void* d_out, int out_size) {
    const float* frames = (const float*)d_in[0];
    const float* W_ih   = (const float*)d_in[1];
    const float* W_hh   = (const float*)d_in[2];
    const float* b_ih   = (const float*)d_in[3];
    const float* b_hh   = (const float*)d_in[4];
    const float* fc_w   = (const float*)d_in[5];
    const float* fc_b   = (const float*)d_in[6];
    float* out = (float*)d_out;

    init_kernel<<<4, 256>>>();

    dim3 g1(GATES / BN, T_STEPS / BM);   // (32, 4) = 128 CTAs
    gemm1_kernel<<<g1, 256>>>(frames, W_ih, b_ih, b_hh);

    scan_kernel<<<SCAN_CTAS, 256>>>(W_hh);

    final_kernel<<<12288 / 16, 256>>>(fc_w, fc_b, out);
}